// round 8
// baseline (speedup 1.0000x reference)
#include <cuda_runtime.h>
#include <cstdint>

#define N_NODES 50000
#define E_EDGES 800000
#define F       128
#define KTOP    32
#define ESTRIDE 64

// Scratch (allocation-free rule: __device__ globals)
__device__ float  g_agg[N_NODES * F];        // 25.6 MB aggregate (fully written by gather)
__device__ int    g_ecnt[N_NODES];
__device__ int    g_ebuf[N_NODES * ESTRIDE];
__device__ float2 g_pack[N_NODES * KTOP];    // (deduped value, idx bits) per topk slot
__device__ uint32_t g_Wr[2 * F * F];         // tf32-rounded [Ws; Wn], 256KB

__device__ __forceinline__ uint32_t smem_u32(const void* p) {
    uint32_t a;
    asm("{ .reg .u64 t; cvta.to.shared.u64 t, %1; cvt.u32.u64 %0, t; }" : "=r"(a) : "l"(p));
    return a;
}
__device__ __forceinline__ uint32_t f2tf32(float f) {
    uint32_t u;
    asm("cvt.rna.tf32.f32 %0, %1;" : "=r"(u) : "f"(f));
    return u;
}

// ---------------------------------------------------------------------------
// Fused prep: (a) dedup topk (last-k-wins, matches XLA scatter-set lane race)
// and pack into float2; (b) bucket edges by dst; (c) tf32-round W into g_Wr.
// All sections independent, grid-stride over the largest (n*32 = 1.6M).
// ---------------------------------------------------------------------------
__global__ void prep_kernel(const float* __restrict__ vals,
                            const int* __restrict__ idxs,
                            const int* __restrict__ src,
                            const int* __restrict__ dst,
                            const float* __restrict__ Ws,
                            const float* __restrict__ Wn,
                            int n, int e) {
    int gid = blockIdx.x * blockDim.x + threadIdx.x;

    // (a) topk dedup+pack: warp per row
    {
        int warp = gid >> 5;
        int lane = gid & 31;
        if (warp < n) {
            int   idx = idxs[warp * KTOP + lane];
            float v   = vals[warp * KTOP + lane];
            unsigned mask = __match_any_sync(0xffffffffu, idx);
            int highest = 31 - __clz(mask);
            float keep = (lane == highest) ? v : 0.0f;
            g_pack[warp * KTOP + lane] = make_float2(keep, __int_as_float(idx));
        }
    }
    // (b) edge bucket
    if (gid < e) {
        int d = dst[gid];
        int p = atomicAdd(&g_ecnt[d], 1);
        if (p < ESTRIDE) g_ebuf[d * ESTRIDE + p] = src[gid];
    }
    // (c) W rounding: rows 0-127 = Ws, 128-255 = Wn (row-major, k-major rows)
    if (gid < F * F) {
        g_Wr[gid]         = f2tf32(Ws[gid]);
        g_Wr[F * F + gid] = f2tf32(Wn[gid]);
    }
}

// ---------------------------------------------------------------------------
// gather: one warp per dst node. 8 rotating smem accumulator rows per warp:
// edges i..i+7 go to acc rows 0..7 (cross-edge smem RMWs provably disjoint,
// within an edge dedup guarantees distinct columns). Group i+8..i+15 is
// prefetched while group i accumulates (MLP=8). Reduce + scale + tf32-round
// at writeout (so the GEMM's A-side truncation of agg is exact).
// ---------------------------------------------------------------------------
__global__ __launch_bounds__(256)
void gather_kernel(int n) {
    __shared__ float acc[8][8][F];   // 32 KB
    int warp = threadIdx.x >> 5;
    int lane = threadIdx.x & 31;
    int d = blockIdx.x * 8 + warp;
    if (d >= n) return;

    float4 z4 = make_float4(0.f, 0.f, 0.f, 0.f);
#pragma unroll
    for (int j = 0; j < 8; j++)
        *(float4*)&acc[warp][j][lane * 4] = z4;

    int cnt = g_ecnt[d];
    const int* eb = &g_ebuf[d * ESTRIDE];
    int lim = cnt < ESTRIDE ? cnt : ESTRIDE;
    int s0 = (lane      < lim) ? eb[lane]      : 0;
    int s1 = (lane + 32 < lim) ? eb[lane + 32] : 0;

    float2 pcur[8];
#pragma unroll
    for (int j = 0; j < 8; j++) {
        if (j < lim) {
            int s = __shfl_sync(0xffffffffu, s0, j);
            pcur[j] = g_pack[(size_t)s * KTOP + lane];
        } else pcur[j] = make_float2(0.f, 0.f);
    }

    for (int i = 0; i < lim; i += 8) {
        float2 pnext[8];
#pragma unroll
        for (int j = 0; j < 8; j++) {
            int ei = i + 8 + j;
            if (ei < lim) {
                int s = __shfl_sync(0xffffffffu, (ei < 32) ? s0 : s1, ei & 31);
                pnext[j] = g_pack[(size_t)s * KTOP + lane];
            } else pnext[j] = make_float2(0.f, 0.f);
        }
#pragma unroll
        for (int j = 0; j < 8; j++) {
            if (pcur[j].x != 0.0f) {
                int c = __float_as_int(pcur[j].y);
                acc[warp][j][c] += pcur[j].x;
            }
        }
#pragma unroll
        for (int j = 0; j < 8; j++) pcur[j] = pnext[j];
    }
    __syncwarp();

    float w = 1.0f / (float)(cnt > 0 ? cnt : 1);
    float4 s = make_float4(0.f, 0.f, 0.f, 0.f);
#pragma unroll
    for (int j = 0; j < 8; j++) {
        float4 a = *(float4*)&acc[warp][j][lane * 4];
        s.x += a.x; s.y += a.y; s.z += a.z; s.w += a.w;
    }
    uint4 o;
    o.x = f2tf32(s.x * w); o.y = f2tf32(s.y * w);
    o.z = f2tf32(s.z * w); o.w = f2tf32(s.w * w);
    *(uint4*)&g_agg[(size_t)d * F + lane * 4] = o;
}

// ---------------------------------------------------------------------------
// tf32 mma.sync fused GEMM, 3-stage cp.async pipeline:
//   out[M,128] = [feat|agg][M,256] @ [Ws;Wn] + bias
// CTA: 128x128 tile, 8 warps (2x4), warp tile 64x32, m16n8k8 HMMA.
// A-side raw f32 bits (feat truncated; agg pre-rounded), B-side pre-rounded.
// ---------------------------------------------------------------------------
#define SA_STRIDE 36
#define SB_STRIDE 136
#define SA_BUF (128 * SA_STRIDE)              // u32 per stage
#define SB_BUF (32 * SB_STRIDE)
#define SMEM_BYTES ((3 * SA_BUF + 3 * SB_BUF) * 4)   // 107520 B

__device__ __forceinline__ void cp16(uint32_t saddr, const void* g, int pbytes) {
    asm volatile("cp.async.ca.shared.global [%0], [%1], 16, %2;"
                 :: "r"(saddr), "l"(g), "r"(pbytes));
}
__device__ __forceinline__ void mma_tf32(float* d, const uint32_t* a, const uint32_t* b) {
    asm volatile("mma.sync.aligned.m16n8k8.row.col.f32.tf32.tf32.f32 "
                 "{%0,%1,%2,%3}, {%4,%5,%6,%7}, {%8,%9}, {%0,%1,%2,%3};"
                 : "+f"(d[0]), "+f"(d[1]), "+f"(d[2]), "+f"(d[3])
                 : "r"(a[0]), "r"(a[1]), "r"(a[2]), "r"(a[3]),
                   "r"(b[0]), "r"(b[1]));
}

__global__ __launch_bounds__(256, 2)
void gemm_mma_kernel(const float* __restrict__ feat,
                     const float* __restrict__ bias,
                     float* __restrict__ out, int n) {
    extern __shared__ uint32_t dsm[];
    uint32_t* sA = dsm;                 // [3][SA_BUF]
    uint32_t* sB = dsm + 3 * SA_BUF;    // [3][SB_BUF]
    uint32_t sA_addr = smem_u32(sA);
    uint32_t sB_addr = smem_u32(sB);

    int tid    = threadIdx.x;
    int wid    = tid >> 5;
    int lane   = tid & 31;
    int warp_m = wid & 1;
    int warp_n = wid >> 1;
    int r0     = blockIdx.x * 128;
    int qr     = lane >> 2;
    int qc     = lane & 3;

    int a_row[4], a_q[4], b_k[4], b_q[4];
#pragma unroll
    for (int l = 0; l < 4; l++) {
        int idx = tid + l * 256;
        a_row[l] = idx >> 3;  a_q[l] = idx & 7;
        b_k[l]   = idx >> 5;  b_q[l] = idx & 31;
    }

    float acc[4][4][4];
#pragma unroll
    for (int mt = 0; mt < 4; mt++)
#pragma unroll
        for (int nt = 0; nt < 4; nt++)
#pragma unroll
            for (int r = 0; r < 4; r++) acc[mt][nt][r] = 0.0f;

    auto issue_chunk = [&](int c, int buf) {
        const float* Asrc = (c < 4) ? feat : g_agg;
        const uint32_t* Bsrc = g_Wr + (c < 4 ? 0 : F * F);
        int kq = (c & 3) * 32;
#pragma unroll
        for (int l = 0; l < 4; l++) {
            int grow = r0 + a_row[l];
            int pb = (grow < n) ? 16 : 0;
            const float* g = &Asrc[(size_t)(grow < n ? grow : 0) * F + kq + a_q[l] * 4];
            cp16(sA_addr + (buf * SA_BUF + a_row[l] * SA_STRIDE + a_q[l] * 4) * 4, g, pb);
        }
#pragma unroll
        for (int l = 0; l < 4; l++) {
            const uint32_t* g = &Bsrc[(size_t)(kq + b_k[l]) * F + b_q[l] * 4];
            cp16(sB_addr + (buf * SB_BUF + b_k[l] * SB_STRIDE + b_q[l] * 4) * 4, g, 16);
        }
        asm volatile("cp.async.commit_group;" ::: "memory");
    };

    issue_chunk(0, 0);
    issue_chunk(1, 1);

    for (int c = 0; c < 8; c++) {
        int buf = c % 3;
        if (c < 6) {
            issue_chunk(c + 2, (c + 2) % 3);
            asm volatile("cp.async.wait_group 2;" ::: "memory");
        } else if (c < 7) {
            asm volatile("cp.async.wait_group 1;" ::: "memory");
        } else {
            asm volatile("cp.async.wait_group 0;" ::: "memory");
        }
        __syncthreads();

        const uint32_t* cA = &sA[buf * SA_BUF];
        const uint32_t* cB = &sB[buf * SB_BUF];
#pragma unroll
        for (int ks = 0; ks < 4; ks++) {
            int k8 = ks * 8;
            uint32_t a[4][4];
#pragma unroll
            for (int mt = 0; mt < 4; mt++) {
                int mrow = warp_m * 64 + mt * 16;
                a[mt][0] = cA[(mrow + qr    ) * SA_STRIDE + k8 + qc    ];
                a[mt][1] = cA[(mrow + qr + 8) * SA_STRIDE + k8 + qc    ];
                a[mt][2] = cA[(mrow + qr    ) * SA_STRIDE + k8 + qc + 4];
                a[mt][3] = cA[(mrow + qr + 8) * SA_STRIDE + k8 + qc + 4];
            }
            uint32_t b[4][2];
#pragma unroll
            for (int nt = 0; nt < 4; nt++) {
                int ncol = warp_n * 32 + nt * 8;
                b[nt][0] = cB[(k8 + qc    ) * SB_STRIDE + ncol + qr];
                b[nt][1] = cB[(k8 + qc + 4) * SB_STRIDE + ncol + qr];
            }
#pragma unroll
            for (int mt = 0; mt < 4; mt++)
#pragma unroll
                for (int nt = 0; nt < 4; nt++)
                    mma_tf32(acc[mt][nt], a[mt], b[nt]);
        }
        __syncthreads();
    }

    // Epilogue: c0/c1 @ (row qr, col 2qc/2qc+1), c2/c3 @ row qr+8
#pragma unroll
    for (int mt = 0; mt < 4; mt++) {
        int row0 = r0 + warp_m * 64 + mt * 16 + qr;
#pragma unroll
        for (int nt = 0; nt < 4; nt++) {
            int col = warp_n * 32 + nt * 8 + qc * 2;
            float b0 = __ldg(&bias[col]);
            float b1 = __ldg(&bias[col + 1]);
            if (row0 < n) {
                float2 o = make_float2(acc[mt][nt][0] + b0, acc[mt][nt][1] + b1);
                *(float2*)&out[(size_t)row0 * F + col] = o;
            }
            if (row0 + 8 < n) {
                float2 o = make_float2(acc[mt][nt][2] + b0, acc[mt][nt][3] + b1);
                *(float2*)&out[(size_t)(row0 + 8) * F + col] = o;
            }
        }
    }
}

// ---------------------------------------------------------------------------
// Launch
// Inputs: 0 feat, 1 topk_values, 2 topk_indices, 3 src, 4 dst,
//         5 W_self, 6 b_self, 7 W_neigh.  Output: [N*128] f32.
// ---------------------------------------------------------------------------
extern "C" void kernel_launch(void* const* d_in, const int* in_sizes, int n_in,
                              void* d_out, int out_size) {
    const float* feat = (const float*)d_in[0];
    const float* tkv  = (const float*)d_in[1];
    const int*   tki  = (const int*)  d_in[2];
    const int*   src  = (const int*)  d_in[3];
    const int*   dst  = (const int*)  d_in[4];
    const float* Ws   = (const float*)d_in[5];
    const float* bs   = (const float*)d_in[6];
    const float* Wn   = (const float*)d_in[7];
    float* out = (float*)d_out;

    const int n = N_NODES;
    const int e = E_EDGES;

    cudaFuncSetAttribute(gemm_mma_kernel,
                         cudaFuncAttributeMaxDynamicSharedMemorySize,
                         SMEM_BYTES);

    void* ecnt_ptr = nullptr;
    cudaGetSymbolAddress(&ecnt_ptr, g_ecnt);
    cudaMemsetAsync(ecnt_ptr, 0, (size_t)n * sizeof(int), 0);

    prep_kernel<<<(n * 32 + 255) / 256, 256>>>(tkv, tki, src, dst, Ws, Wn, n, e);
    gather_kernel<<<(n + 7) / 8, 256>>>(n);
    gemm_mma_kernel<<<(n + 127) / 128, 256, SMEM_BYTES>>>(feat, bs, out, n);
}